// round 12
// baseline (speedup 1.0000x reference)
#include <cuda_runtime.h>
#include <cstdint>
#include <math.h>

#define BB   8
#define CC   256
#define KCC  32
#define NN   16384
#define TPX  128          // pass1 tile pixels
#define T1   8            // tiles per CTA
#define NB1  16           // CTAs per batch (16*8*128 = 16384) -> 128 CTAs = 1 wave
#define TP   64           // pass2 tile pixels
#define XLD  68

#define LDW  260          // Ws row stride (floats): conflict-free A frags
#define LDX  136          // xs row stride: conflict-free stage-B B frags
#define LDK  132          // km row stride: conflict-free stage-C A frags

// smem float offsets (pass1)
#define F_BIAS 0
#define F_MBAR 64                         // 8 mbarriers (64 bytes = 16 floats)
#define F_WS   80
#define F_XS   (F_WS + 64 * LDW)          // 16720
#define F_KM   (F_XS + 256 * LDX)         // 51536
#define SMEM1_FLOATS (F_KM + 32 * LDK)    // 55760
#define SMEM1_BYTES  (SMEM1_FLOATS * 4)   // 223040

// Scratch (device globals)
__device__ __align__(16) float g_qm[(size_t)BB * KCC * NN]; // 16 MB fp32 [b][kc][n]
__device__ __align__(16) float g_S [BB * KCC * CC];
__device__ __align__(16) float g_z [BB * KCC];
__device__ __align__(16) float g_kv[BB * KCC * CC];
__device__ __align__(16) float g_zf[BB * KCC];

extern __shared__ float smf[];

__device__ __forceinline__ uint32_t smem_u32(const void* p) {
    uint32_t a;
    asm("{ .reg .u64 t; cvta.to.shared.u64 t, %1; cvt.u32.u64 %0, t; }" : "=r"(a) : "l"(p));
    return a;
}
__device__ __forceinline__ void mma_tf32(float d[4], const uint32_t a[4], const uint32_t b[2]) {
    asm volatile(
        "mma.sync.aligned.m16n8k8.row.col.f32.tf32.tf32.f32 "
        "{%0,%1,%2,%3}, {%4,%5,%6,%7}, {%8,%9}, {%0,%1,%2,%3};\n"
        : "+f"(d[0]), "+f"(d[1]), "+f"(d[2]), "+f"(d[3])
        : "r"(a[0]), "r"(a[1]), "r"(a[2]), "r"(a[3]), "r"(b[0]), "r"(b[1]));
}

// packed fp32x2 ops (Blackwell FFMA2 path; PTX-only)
__device__ __forceinline__ unsigned long long pack2(float v) {
    unsigned long long r;
    asm("mov.b64 %0, {%1, %1};" : "=l"(r) : "f"(v));
    return r;
}
__device__ __forceinline__ void fma2(unsigned long long& d, unsigned long long a,
                                     unsigned long long b) {
    asm("fma.rn.f32x2 %0, %1, %2, %0;" : "+l"(d) : "l"(a), "l"(b));
}
__device__ __forceinline__ void unpack2(float& lo, float& hi, unsigned long long v) {
    asm("mov.b64 {%0, %1}, %2;" : "=f"(lo), "=f"(hi) : "l"(v));
}

// mbarrier + 1D TMA bulk copy helpers
#define MBAR_INIT(a, n) \
    asm volatile("mbarrier.init.shared.b64 [%0], %1;" :: "r"(a), "r"((uint32_t)(n)) : "memory")
#define MBAR_EXPECT_TX(a, bytes) \
    asm volatile("mbarrier.arrive.expect_tx.shared.b64 _, [%0], %1;" :: "r"(a), "r"((uint32_t)(bytes)) : "memory")
#define MBAR_WAIT(a, ph) do {                                                                     \
    uint32_t _m = (a), _p = (ph), _d = 0;                                                         \
    while (!_d) {                                                                                 \
        asm volatile("{ .reg .pred p; mbarrier.try_wait.parity.acquire.cta.shared::cta.b64 p, [%1], %2, 0x989680;" \
                     " selp.b32 %0, 1, 0, p; }" : "=r"(_d) : "r"(_m), "r"(_p) : "memory");        \
    } } while (0)

__device__ __forceinline__ void bulk_g2s(uint32_t dst, const void* src, uint32_t bytes,
                                         uint32_t mbar) {
    asm volatile(
        "cp.async.bulk.shared::cluster.global.mbarrier::complete_tx::bytes [%0], [%1], %2, [%3];"
        :: "r"(dst), "l"(src), "r"(bytes), "r"(mbar) : "memory");
}

// ---------------------------------------------------------------------------
__global__ void zero_kernel() {
    int i = blockIdx.x * 256 + threadIdx.x;
    if (i < BB * KCC * CC) g_S[i] = 0.f;
    if (i < BB * KCC) g_z[i] = 0.f;
}

// ---------------------------------------------------------------------------
// Pass 1 (tf32 mma, 256 threads / 8 warps, 1-wave grid)
//   TMA bulk chunk loader (warp j owns chunk j; mbarrier data-ready waits)
// ---------------------------------------------------------------------------
__global__ __launch_bounds__(256, 1)
void pass1_kernel(const float* __restrict__ x,
                  const float* __restrict__ Wq, const float* __restrict__ bq,
                  const float* __restrict__ Wk, const float* __restrict__ bk)
{
    const int tid  = threadIdx.x;
    const int b    = blockIdx.y;
    const int blk  = blockIdx.x;
    const int w    = tid >> 5;
    const int lane = tid & 31;
    const int g    = lane >> 2;
    const int t    = lane & 3;

    const uint32_t sb   = smem_u32(smf);
    const uint32_t mbar = sb + F_MBAR * 4;     // 8 x u64
    const uint32_t* WsU = (const uint32_t*)(smf + F_WS);
    const uint32_t* xsU = (const uint32_t*)(smf + F_XS);
    const uint32_t* kmU = (const uint32_t*)(smf + F_KM);

    if (tid == 0) {
#pragma unroll
        for (int j = 0; j < 8; j++) MBAR_INIT(mbar + j * 8, 1);
    }
    if (tid < 64) smf[F_BIAS + tid] = (tid < KCC) ? bq[tid] : bk[tid - KCC];
    for (int i = tid; i < 64 * 256; i += 256) {
        int qk = i >> 8, c = i & 255;
        smf[F_WS + qk * LDW + c] = (qk < KCC) ? Wq[qk * CC + c] : Wk[(qk - KCC) * CC + c];
    }

    float sc[2][4][4];
#pragma unroll
    for (int mi = 0; mi < 2; mi++)
#pragma unroll
        for (int nj = 0; nj < 4; nj++)
#pragma unroll
            for (int r = 0; r < 4; r++) sc[mi][nj][r] = 0.f;
    float zp[4] = {0.f, 0.f, 0.f, 0.f};

    const int qk0   = (w >> 2) * 32;
    const int px0   = (w & 3) * 32;
    const int cbase = w * 32;

    const float* xbase = x + (size_t)b * CC * NN;

    __syncthreads();   // mbar init + Ws/bias ready

    // Prologue: warp w issues its chunk (c rows w*32..w*32+31) for tile 0
    if (lane == 0) {
        const uint32_t mb = mbar + w * 8;
        MBAR_EXPECT_TX(mb, 32 * TPX * 4);
        const float* src = xbase + (size_t)blk * T1 * TPX + (size_t)(w * 32) * NN;
        uint32_t dst = sb + (uint32_t)(F_XS + (w * 32) * LDX) * 4;
#pragma unroll
        for (int r = 0; r < 32; r++)
            bulk_g2s(dst + (uint32_t)r * (LDX * 4), src + (size_t)r * NN, TPX * 4, mb);
    }

    for (int tt = 0; tt < T1; tt++) {
        const int n0 = (blk * T1 + tt) * TPX;

        float db[2][4][4];
#pragma unroll
        for (int mi = 0; mi < 2; mi++)
#pragma unroll
            for (int nj = 0; nj < 4; nj++)
#pragma unroll
                for (int r = 0; r < 4; r++) db[mi][nj][r] = 0.f;

#pragma unroll
        for (int j = 0; j < 8; j++) {
            MBAR_WAIT(mbar + j * 8, tt & 1);
#pragma unroll
            for (int ss = 0; ss < 4; ss++) {
                const int c0 = j * 32 + ss * 8;
                uint32_t a[2][4];
#pragma unroll
                for (int mi = 0; mi < 2; mi++) {
                    int r0 = qk0 + 16 * mi + g;
                    a[mi][0] = WsU[r0 * LDW + c0 + t];
                    a[mi][1] = WsU[(r0 + 8) * LDW + c0 + t];
                    a[mi][2] = WsU[r0 * LDW + c0 + t + 4];
                    a[mi][3] = WsU[(r0 + 8) * LDW + c0 + t + 4];
                }
#pragma unroll
                for (int nj = 0; nj < 4; nj++) {
                    uint32_t bb[2];
                    bb[0] = xsU[(c0 + t) * LDX + px0 + 8 * nj + g];
                    bb[1] = xsU[(c0 + t + 4) * LDX + px0 + 8 * nj + g];
                    mma_tf32(db[0][nj], a[0], bb);
                    mma_tf32(db[1][nj], a[1], bb);
                }
            }
        }

        // ---- Epilogue: bias + elu + 1, float2 vectorized stores ----
        if (w < 4) {
#pragma unroll
            for (int mi = 0; mi < 2; mi++)
#pragma unroll
                for (int nj = 0; nj < 4; nj++)
#pragma unroll
                    for (int h = 0; h < 2; h++) {
                        int qk = 16 * mi + g + 8 * h;
                        int px = px0 + 8 * nj + 2 * t;
                        float bqk = smf[F_BIAS + qk];
                        float v0 = db[mi][nj][2 * h]     + bqk;
                        float v1 = db[mi][nj][2 * h + 1] + bqk;
                        v0 = (v0 > 0.f) ? (v0 + 1.f) : __expf(v0);
                        v1 = (v1 > 0.f) ? (v1 + 1.f) : __expf(v1);
                        *(float2*)&g_qm[((size_t)b * KCC + qk) * NN + n0 + px] =
                            make_float2(v0, v1);
                    }
        } else {
#pragma unroll
            for (int mi = 0; mi < 2; mi++)
#pragma unroll
                for (int nj = 0; nj < 4; nj++)
#pragma unroll
                    for (int h = 0; h < 2; h++) {
                        int kc = 16 * mi + g + 8 * h;
                        int px = px0 + 8 * nj + 2 * t;
                        float bkc = smf[F_BIAS + 32 + kc];
                        float v0 = db[mi][nj][2 * h]     + bkc;
                        float v1 = db[mi][nj][2 * h + 1] + bkc;
                        v0 = (v0 > 0.f) ? (v0 + 1.f) : __expf(v0);
                        v1 = (v1 > 0.f) ? (v1 + 1.f) : __expf(v1);
                        *(float2*)&smf[F_KM + kc * LDK + px] = make_float2(v0, v1);
                        zp[mi * 2 + h] += v0 + v1;
                    }
        }
        __syncthreads();   // km visible; all stage-B reads of xs complete

        // ---- Stage C: warp w reads ONLY xs rows [32w, 32w+32) ----
#pragma unroll 4
        for (int s = 0; s < 16; s++) {
            const int p0 = s * 8;
            uint32_t a[2][4];
#pragma unroll
            for (int mi = 0; mi < 2; mi++) {
                int r0 = 16 * mi + g;
                a[mi][0] = kmU[r0 * LDK + p0 + t];
                a[mi][1] = kmU[(r0 + 8) * LDK + p0 + t];
                a[mi][2] = kmU[r0 * LDK + p0 + t + 4];
                a[mi][3] = kmU[(r0 + 8) * LDK + p0 + t + 4];
            }
#pragma unroll
            for (int nj = 0; nj < 4; nj++) {
                uint32_t bb[2];
                bb[0] = xsU[(cbase + 8 * nj + g) * LDX + p0 + t];
                bb[1] = xsU[(cbase + 8 * nj + g) * LDX + p0 + t + 4];
                mma_tf32(sc[0][nj], a[0], bb);
                mma_tf32(sc[1][nj], a[1], bb);
            }
        }

        // Warp w done with xs chunk w -> issue next tile's chunk w immediately
        if (tt + 1 < T1 && lane == 0) {
            const uint32_t mb = mbar + w * 8;
            MBAR_EXPECT_TX(mb, 32 * TPX * 4);
            const float* src = xbase + (size_t)(blk * T1 + tt + 1) * TPX
                             + (size_t)(w * 32) * NN;
            uint32_t dst = sb + (uint32_t)(F_XS + (w * 32) * LDX) * 4;
#pragma unroll
            for (int r = 0; r < 32; r++)
                bulk_g2s(dst + (uint32_t)r * (LDX * 4), src + (size_t)r * NN, TPX * 4, mb);
        }
        __syncthreads();   // protect km from next tile's epilogue
    }

#pragma unroll
    for (int mi = 0; mi < 2; mi++)
#pragma unroll
        for (int nj = 0; nj < 4; nj++)
#pragma unroll
            for (int r = 0; r < 4; r++) {
                int kc = 16 * mi + g + 8 * (r >> 1);
                int c  = cbase + 8 * nj + 2 * t + (r & 1);
                atomicAdd(&g_S[(b * KCC + kc) * CC + c], sc[mi][nj][r]);
            }
    if (w >= 4) {
#pragma unroll
        for (int i = 0; i < 4; i++) {
            float v = zp[i];
            v += __shfl_xor_sync(0xffffffffu, v, 1);
            v += __shfl_xor_sync(0xffffffffu, v, 2);
            if (t == 0) {
                int kc = 16 * (i >> 1) + 8 * (i & 1) + g;
                atomicAdd(&g_z[b * KCC + kc], v);
            }
        }
    }
}

// ---------------------------------------------------------------------------
// kv = S @ Wv^T + z * bv^T
// ---------------------------------------------------------------------------
__global__ __launch_bounds__(256)
void kv_kernel(const float* __restrict__ Wv, const float* __restrict__ bv)
{
    __shared__ float Ssm[KCC * CC];
    __shared__ float Wsm[32 * CC];
    __shared__ float zsm[KCC];

    const int tid = threadIdx.x;
    const int b   = blockIdx.y;
    const int v0  = blockIdx.x * 32;

    for (int i = tid; i < KCC * CC / 4; i += 256)
        *(float4*)&Ssm[i * 4] = *(const float4*)&g_S[b * KCC * CC + i * 4];
    for (int i = tid; i < 32 * CC / 4; i += 256)
        *(float4*)&Wsm[i * 4] = *(const float4*)&Wv[v0 * CC + i * 4];
    if (tid < KCC) {
        float z = g_z[b * KCC + tid];
        zsm[tid] = z;
        if (blockIdx.x == 0) g_zf[b * KCC + tid] = z;
    }
    __syncthreads();

    const int kc = tid >> 3, j0 = tid & 7;
#pragma unroll
    for (int j = 0; j < 4; j++) {
        int vl = j0 + 8 * j;
        float acc = zsm[kc] * bv[v0 + vl];
        const float* wr = Wsm + vl * CC;
        const float* sr = Ssm + kc * CC;
#pragma unroll 8
        for (int c4 = 0; c4 < 64; c4++) {
            float4 wv = *(const float4*)&wr[c4 * 4];
            float4 s  = *(const float4*)&sr[c4 * 4];
            acc = fmaf(wv.x, s.x, acc);
            acc = fmaf(wv.y, s.y, acc);
            acc = fmaf(wv.z, s.z, acc);
            acc = fmaf(wv.w, s.w, acc);
        }
        g_kv[(b * KCC + kc) * CC + v0 + vl] = acc;
    }
}

// ---------------------------------------------------------------------------
// Pass 2 (packed f32x2 FMA, reg-capped for 4 CTAs/SM)
// ---------------------------------------------------------------------------
__global__ __launch_bounds__(256, 4)
void pass2_kernel(const float* __restrict__ x,
                  const float* __restrict__ gamma,
                  float* __restrict__ out)
{
    __shared__ float kvh[KCC * 128];
    __shared__ float qms[KCC * XLD];
    __shared__ float invq[TP];
    __shared__ float zsm[KCC];

    const int tid  = threadIdx.x;
    const int b    = blockIdx.z;
    const int half = blockIdx.y;
    const int n0   = blockIdx.x * TP;
    const int ty   = tid >> 4;
    const int tx   = tid & 15;

    for (int i = tid; i < KCC * 32; i += 256) {
        int k = i >> 5, c4 = i & 31;
        *(float4*)&kvh[k * 128 + c4 * 4] =
            *(const float4*)&g_kv[(b * KCC + k) * CC + half * 128 + c4 * 4];
    }
    for (int i = tid; i < KCC * 16; i += 256) {
        int k = i >> 4, fx = i & 15;
        *(float4*)&qms[k * XLD + fx * 4] =
            *(const float4*)&g_qm[((size_t)b * KCC + k) * NN + n0 + fx * 4];
    }
    if (tid < KCC) zsm[tid] = g_zf[b * KCC + tid];
    __syncthreads();

    if (tid < TP) {
        float s = 0.f;
#pragma unroll
        for (int k = 0; k < KCC; k++) s = fmaf(zsm[k], qms[k * XLD + tid], s);
        invq[tid] = gamma[0] / fmaxf(s, 1e-6f);
    }
    __syncthreads();

    unsigned long long acc2[4][4];
#pragma unroll
    for (int ci = 0; ci < 4; ci++)
#pragma unroll
        for (int pj = 0; pj < 4; pj++) acc2[ci][pj] = 0ull;

#pragma unroll 4
    for (int k = 0; k < KCC; k++) {
        float4 p = *(float4*)&qms[k * XLD + tx * 4];
        unsigned long long px2[4];
        px2[0] = pack2(p.x);
        px2[1] = pack2(p.y);
        px2[2] = pack2(p.z);
        px2[3] = pack2(p.w);
        ulonglong2 A0 = *(const ulonglong2*)&kvh[k * 128 + ty * 8];
        ulonglong2 A1 = *(const ulonglong2*)&kvh[k * 128 + ty * 8 + 4];
#pragma unroll
        for (int pj = 0; pj < 4; pj++) {
            fma2(acc2[0][pj], A0.x, px2[pj]);
            fma2(acc2[1][pj], A0.y, px2[pj]);
            fma2(acc2[2][pj], A1.x, px2[pj]);
            fma2(acc2[3][pj], A1.y, px2[pj]);
        }
    }

    float iv[4];
#pragma unroll
    for (int j = 0; j < 4; j++) iv[j] = invq[tx * 4 + j];

#pragma unroll
    for (int ci = 0; ci < 4; ci++) {
        float lo[4], hi[4];
#pragma unroll
        for (int pj = 0; pj < 4; pj++) unpack2(lo[pj], hi[pj], acc2[ci][pj]);

        int c0 = half * 128 + ty * 8 + 2 * ci;
        size_t gx0 = ((size_t)b * CC + c0) * NN + n0 + tx * 4;
        float4 xv0 = *(const float4*)&x[gx0];
        float4 o0;
        o0.x = fmaf(lo[0], iv[0], xv0.x);
        o0.y = fmaf(lo[1], iv[1], xv0.y);
        o0.z = fmaf(lo[2], iv[2], xv0.z);
        o0.w = fmaf(lo[3], iv[3], xv0.w);
        *(float4*)&out[gx0] = o0;

        size_t gx1 = gx0 + NN;
        float4 xv1 = *(const float4*)&x[gx1];
        float4 o1;
        o1.x = fmaf(hi[0], iv[0], xv1.x);
        o1.y = fmaf(hi[1], iv[1], xv1.y);
        o1.z = fmaf(hi[2], iv[2], xv1.z);
        o1.w = fmaf(hi[3], iv[3], xv1.w);
        *(float4*)&out[gx1] = o1;
    }
}

// ---------------------------------------------------------------------------
extern "C" void kernel_launch(void* const* d_in, const int* in_sizes, int n_in,
                              void* d_out, int out_size)
{
    const float* x     = (const float*)d_in[0];
    const float* Wq    = (const float*)d_in[1];
    const float* bq    = (const float*)d_in[2];
    const float* Wk    = (const float*)d_in[3];
    const float* bk    = (const float*)d_in[4];
    const float* Wv    = (const float*)d_in[5];
    const float* bv    = (const float*)d_in[6];
    const float* gamma = (const float*)d_in[7];
    float* out = (float*)d_out;

    cudaFuncSetAttribute(pass1_kernel, cudaFuncAttributeMaxDynamicSharedMemorySize,
                         SMEM1_BYTES);

    zero_kernel<<<(BB * KCC * CC + 255) / 256, 256>>>();
    pass1_kernel<<<dim3(NB1, BB), 256, SMEM1_BYTES>>>(x, Wq, bq, Wk, bk);
    kv_kernel<<<dim3(8, BB), 256>>>(Wv, bv);
    pass2_kernel<<<dim3(NN / TP, 2, BB), 256>>>(x, gamma, out);
}

// round 13
// speedup vs baseline: 1.0803x; 1.0803x over previous
#include <cuda_runtime.h>
#include <cstdint>
#include <math.h>

#define BB   8
#define CC   256
#define KCC  32
#define NN   16384
#define TPX  128          // pass1 tile pixels
#define NTILES (BB * NN / TPX)   // 1024 flat tiles
#define GRID1 148                // one CTA per SM
#define TP   64           // pass2 tile pixels
#define XLD  68

#define LDW  260          // Ws row stride (floats): conflict-free A frags
#define LDX  136          // xs row stride: conflict-free stage-B B frags
#define LDK  132          // km row stride: conflict-free stage-C A frags

// smem float offsets (pass1)
#define F_BIAS 0
#define F_WS   64
#define F_XS   (F_WS + 64 * LDW)          // 16704
#define F_KM   (F_XS + 256 * LDX)         // 51520
#define SMEM1_FLOATS (F_KM + 32 * LDK)    // 55744
#define SMEM1_BYTES  (SMEM1_FLOATS * 4)   // 222976

// Scratch (device globals)
__device__ __align__(16) float g_qm[(size_t)BB * KCC * NN]; // 16 MB fp32 [b][kc][n]
__device__ __align__(16) float g_S [BB * KCC * CC];
__device__ __align__(16) float g_z [BB * KCC];
__device__ __align__(16) float g_kv[BB * KCC * CC];
__device__ __align__(16) float g_zf[BB * KCC];

extern __shared__ float smf[];

__device__ __forceinline__ void cp_async16(uint32_t smem_dst, const void* gmem_src) {
    asm volatile("cp.async.cg.shared.global [%0], [%1], 16;\n" :: "r"(smem_dst), "l"(gmem_src));
}
__device__ __forceinline__ void cp_commit() {
    asm volatile("cp.async.commit_group;\n");
}
__device__ __forceinline__ void cp_wait_n(int n) {
    switch (n) {
        case 0: asm volatile("cp.async.wait_group 0;\n"); break;
        case 1: asm volatile("cp.async.wait_group 1;\n"); break;
        case 2: asm volatile("cp.async.wait_group 2;\n"); break;
        case 3: asm volatile("cp.async.wait_group 3;\n"); break;
        case 4: asm volatile("cp.async.wait_group 4;\n"); break;
        case 5: asm volatile("cp.async.wait_group 5;\n"); break;
        case 6: asm volatile("cp.async.wait_group 6;\n"); break;
        default: asm volatile("cp.async.wait_group 7;\n"); break;
    }
}
__device__ __forceinline__ uint32_t smem_u32(const void* p) {
    uint32_t a;
    asm("{ .reg .u64 t; cvta.to.shared.u64 t, %1; cvt.u32.u64 %0, t; }" : "=r"(a) : "l"(p));
    return a;
}
__device__ __forceinline__ void mma_tf32(float d[4], const uint32_t a[4], const uint32_t b[2]) {
    asm volatile(
        "mma.sync.aligned.m16n8k8.row.col.f32.tf32.tf32.f32 "
        "{%0,%1,%2,%3}, {%4,%5,%6,%7}, {%8,%9}, {%0,%1,%2,%3};\n"
        : "+f"(d[0]), "+f"(d[1]), "+f"(d[2]), "+f"(d[3])
        : "r"(a[0]), "r"(a[1]), "r"(a[2]), "r"(a[3]), "r"(b[0]), "r"(b[1]));
}

// packed fp32x2 ops (Blackwell FFMA2 path; PTX-only)
__device__ __forceinline__ unsigned long long pack2(float v) {
    unsigned long long r;
    asm("mov.b64 %0, {%1, %1};" : "=l"(r) : "f"(v));
    return r;
}
__device__ __forceinline__ void fma2(unsigned long long& d, unsigned long long a,
                                     unsigned long long b) {
    asm("fma.rn.f32x2 %0, %1, %2, %0;" : "+l"(d) : "l"(a), "l"(b));
}
__device__ __forceinline__ void unpack2(float& lo, float& hi, unsigned long long v) {
    asm("mov.b64 {%0, %1}, %2;" : "=f"(lo), "=f"(hi) : "l"(v));
}

// ---------------------------------------------------------------------------
__global__ void zero_kernel() {
    int i = blockIdx.x * 256 + threadIdx.x;
    if (i < BB * KCC * CC) g_S[i] = 0.f;
    if (i < BB * KCC) g_z[i] = 0.f;
}

// ---------------------------------------------------------------------------
// Pass 1 (tf32 mma, 256 threads / 8 warps):
//   R13: flat 1024-tile pool over 148 CTAs (balanced 6-7 tiles each);
//        S/z flushed at batch boundaries. cp.async pipeline = proven R10.
// ---------------------------------------------------------------------------
__global__ __launch_bounds__(256, 1)
void pass1_kernel(const float* __restrict__ x,
                  const float* __restrict__ Wq, const float* __restrict__ bq,
                  const float* __restrict__ Wk, const float* __restrict__ bk)
{
    const int tid  = threadIdx.x;
    const int blk  = blockIdx.x;
    const int w    = tid >> 5;
    const int lane = tid & 31;
    const int g    = lane >> 2;
    const int t    = lane & 3;

    const uint32_t sb = smem_u32(smf);
    const uint32_t* WsU = (const uint32_t*)(smf + F_WS);
    const uint32_t* xsU = (const uint32_t*)(smf + F_XS);
    const uint32_t* kmU = (const uint32_t*)(smf + F_KM);

    if (tid < 64) smf[F_BIAS + tid] = (tid < KCC) ? bq[tid] : bk[tid - KCC];
    for (int i = tid; i < 64 * 256; i += 256) {
        int qk = i >> 8, c = i & 255;
        smf[F_WS + qk * LDW + c] = (qk < KCC) ? Wq[qk * CC + c] : Wk[(qk - KCC) * CC + c];
    }

    float sc[2][4][4];
#pragma unroll
    for (int mi = 0; mi < 2; mi++)
#pragma unroll
        for (int nj = 0; nj < 4; nj++)
#pragma unroll
            for (int r = 0; r < 4; r++) sc[mi][nj][r] = 0.f;
    float zp[4] = {0.f, 0.f, 0.f, 0.f};

    const int qk0   = (w >> 2) * 32;
    const int px0   = (w & 3) * 32;
    const int cbase = w * 32;

    const int tstart = (blk * NTILES) / GRID1;
    const int tend   = ((blk + 1) * NTILES) / GRID1;

    // Prologue: issue tile tstart's 8 chunk groups
    {
        int b0 = tstart >> 7;
        const float* xb = x + (size_t)b0 * CC * NN + (size_t)(tstart & 127) * TPX;
#pragma unroll
        for (int j = 0; j < 8; j++) {
            for (int u = tid; u < 1024; u += 256) {
                int row = u >> 5, seg = u & 31;
                int c = j * 32 + row;
                cp_async16(sb + (uint32_t)(F_XS + c * LDX + seg * 4) * 4,
                           xb + (size_t)c * NN + seg * 4);
            }
            cp_commit();
        }
    }
    __syncthreads();   // Ws/bias ready

    for (int tg = tstart; tg < tend; tg++) {
        const int b  = tg >> 7;
        const int n0 = (tg & 127) * TPX;

        float db[2][4][4];
#pragma unroll
        for (int mi = 0; mi < 2; mi++)
#pragma unroll
            for (int nj = 0; nj < 4; nj++)
#pragma unroll
                for (int r = 0; r < 4; r++) db[mi][nj][r] = 0.f;

#pragma unroll
        for (int j = 0; j < 8; j++) {
            cp_wait_n(7 - j);
            __syncthreads();
#pragma unroll
            for (int ss = 0; ss < 4; ss++) {
                const int c0 = j * 32 + ss * 8;
                uint32_t a[2][4];
#pragma unroll
                for (int mi = 0; mi < 2; mi++) {
                    int r0 = qk0 + 16 * mi + g;
                    a[mi][0] = WsU[r0 * LDW + c0 + t];
                    a[mi][1] = WsU[(r0 + 8) * LDW + c0 + t];
                    a[mi][2] = WsU[r0 * LDW + c0 + t + 4];
                    a[mi][3] = WsU[(r0 + 8) * LDW + c0 + t + 4];
                }
#pragma unroll
                for (int nj = 0; nj < 4; nj++) {
                    uint32_t bb[2];
                    bb[0] = xsU[(c0 + t) * LDX + px0 + 8 * nj + g];
                    bb[1] = xsU[(c0 + t + 4) * LDX + px0 + 8 * nj + g];
                    mma_tf32(db[0][nj], a[0], bb);
                    mma_tf32(db[1][nj], a[1], bb);
                }
            }
        }

        // ---- Epilogue: bias + elu + 1, float2 vectorized stores ----
        if (w < 4) {
#pragma unroll
            for (int mi = 0; mi < 2; mi++)
#pragma unroll
                for (int nj = 0; nj < 4; nj++)
#pragma unroll
                    for (int h = 0; h < 2; h++) {
                        int qk = 16 * mi + g + 8 * h;
                        int px = px0 + 8 * nj + 2 * t;
                        float bqk = smf[F_BIAS + qk];
                        float v0 = db[mi][nj][2 * h]     + bqk;
                        float v1 = db[mi][nj][2 * h + 1] + bqk;
                        v0 = (v0 > 0.f) ? (v0 + 1.f) : __expf(v0);
                        v1 = (v1 > 0.f) ? (v1 + 1.f) : __expf(v1);
                        *(float2*)&g_qm[((size_t)b * KCC + qk) * NN + n0 + px] =
                            make_float2(v0, v1);
                    }
        } else {
#pragma unroll
            for (int mi = 0; mi < 2; mi++)
#pragma unroll
                for (int nj = 0; nj < 4; nj++)
#pragma unroll
                    for (int h = 0; h < 2; h++) {
                        int kc = 16 * mi + g + 8 * h;
                        int px = px0 + 8 * nj + 2 * t;
                        float bkc = smf[F_BIAS + 32 + kc];
                        float v0 = db[mi][nj][2 * h]     + bkc;
                        float v1 = db[mi][nj][2 * h + 1] + bkc;
                        v0 = (v0 > 0.f) ? (v0 + 1.f) : __expf(v0);
                        v1 = (v1 > 0.f) ? (v1 + 1.f) : __expf(v1);
                        *(float2*)&smf[F_KM + kc * LDK + px] = make_float2(v0, v1);
                        zp[mi * 2 + h] += v0 + v1;
                    }
        }
        __syncthreads();   // km visible

        // ---- Stage C ----
#pragma unroll 4
        for (int s = 0; s < 16; s++) {
            const int p0 = s * 8;
            uint32_t a[2][4];
#pragma unroll
            for (int mi = 0; mi < 2; mi++) {
                int r0 = 16 * mi + g;
                a[mi][0] = kmU[r0 * LDK + p0 + t];
                a[mi][1] = kmU[(r0 + 8) * LDK + p0 + t];
                a[mi][2] = kmU[r0 * LDK + p0 + t + 4];
                a[mi][3] = kmU[(r0 + 8) * LDK + p0 + t + 4];
            }
#pragma unroll
            for (int nj = 0; nj < 4; nj++) {
                uint32_t bb[2];
                bb[0] = xsU[(cbase + 8 * nj + g) * LDX + p0 + t];
                bb[1] = xsU[(cbase + 8 * nj + g) * LDX + p0 + t + 4];
                mma_tf32(sc[0][nj], a[0], bb);
                mma_tf32(sc[1][nj], a[1], bb);
            }
        }
        __syncthreads();   // xs/km free

        // issue next tile's chunk copies
        if (tg + 1 < tend) {
            int bn = (tg + 1) >> 7;
            const float* xb = x + (size_t)bn * CC * NN + (size_t)((tg + 1) & 127) * TPX;
#pragma unroll
            for (int j = 0; j < 8; j++) {
                for (int u = tid; u < 1024; u += 256) {
                    int row = u >> 5, seg = u & 31;
                    int c = j * 32 + row;
                    cp_async16(sb + (uint32_t)(F_XS + c * LDX + seg * 4) * 4,
                               xb + (size_t)c * NN + seg * 4);
                }
                cp_commit();
            }
        }

        // ---- Flush S/z at batch boundary or end of range ----
        if (tg + 1 >= tend || ((tg + 1) >> 7) != b) {
#pragma unroll
            for (int mi = 0; mi < 2; mi++)
#pragma unroll
                for (int nj = 0; nj < 4; nj++)
#pragma unroll
                    for (int r = 0; r < 4; r++) {
                        int kc = 16 * mi + g + 8 * (r >> 1);
                        int c  = cbase + 8 * nj + 2 * t + (r & 1);
                        atomicAdd(&g_S[(b * KCC + kc) * CC + c], sc[mi][nj][r]);
                        sc[mi][nj][r] = 0.f;
                    }
            if (w >= 4) {
#pragma unroll
                for (int i = 0; i < 4; i++) {
                    float v = zp[i];
                    v += __shfl_xor_sync(0xffffffffu, v, 1);
                    v += __shfl_xor_sync(0xffffffffu, v, 2);
                    if (t == 0) {
                        int kc = 16 * (i >> 1) + 8 * (i & 1) + g;
                        atomicAdd(&g_z[b * KCC + kc], v);
                    }
                    zp[i] = 0.f;
                }
            }
        }
    }
}

// ---------------------------------------------------------------------------
// kv = S @ Wv^T + z * bv^T
// ---------------------------------------------------------------------------
__global__ __launch_bounds__(256)
void kv_kernel(const float* __restrict__ Wv, const float* __restrict__ bv)
{
    __shared__ float Ssm[KCC * CC];
    __shared__ float Wsm[32 * CC];
    __shared__ float zsm[KCC];

    const int tid = threadIdx.x;
    const int b   = blockIdx.y;
    const int v0  = blockIdx.x * 32;

    for (int i = tid; i < KCC * CC / 4; i += 256)
        *(float4*)&Ssm[i * 4] = *(const float4*)&g_S[b * KCC * CC + i * 4];
    for (int i = tid; i < 32 * CC / 4; i += 256)
        *(float4*)&Wsm[i * 4] = *(const float4*)&Wv[v0 * CC + i * 4];
    if (tid < KCC) {
        float z = g_z[b * KCC + tid];
        zsm[tid] = z;
        if (blockIdx.x == 0) g_zf[b * KCC + tid] = z;
    }
    __syncthreads();

    const int kc = tid >> 3, j0 = tid & 7;
#pragma unroll
    for (int j = 0; j < 4; j++) {
        int vl = j0 + 8 * j;
        float acc = zsm[kc] * bv[v0 + vl];
        const float* wr = Wsm + vl * CC;
        const float* sr = Ssm + kc * CC;
#pragma unroll 8
        for (int c4 = 0; c4 < 64; c4++) {
            float4 wv = *(const float4*)&wr[c4 * 4];
            float4 s  = *(const float4*)&sr[c4 * 4];
            acc = fmaf(wv.x, s.x, acc);
            acc = fmaf(wv.y, s.y, acc);
            acc = fmaf(wv.z, s.z, acc);
            acc = fmaf(wv.w, s.w, acc);
        }
        g_kv[(b * KCC + kc) * CC + v0 + vl] = acc;
    }
}

// ---------------------------------------------------------------------------
// Pass 2 (packed f32x2 FMA, reg-capped for 4 CTAs/SM) — unchanged from R10
// ---------------------------------------------------------------------------
__global__ __launch_bounds__(256, 4)
void pass2_kernel(const float* __restrict__ x,
                  const float* __restrict__ gamma,
                  float* __restrict__ out)
{
    __shared__ float kvh[KCC * 128];
    __shared__ float qms[KCC * XLD];
    __shared__ float invq[TP];
    __shared__ float zsm[KCC];

    const int tid  = threadIdx.x;
    const int b    = blockIdx.z;
    const int half = blockIdx.y;
    const int n0   = blockIdx.x * TP;
    const int ty   = tid >> 4;
    const int tx   = tid & 15;

    for (int i = tid; i < KCC * 32; i += 256) {
        int k = i >> 5, c4 = i & 31;
        *(float4*)&kvh[k * 128 + c4 * 4] =
            *(const float4*)&g_kv[(b * KCC + k) * CC + half * 128 + c4 * 4];
    }
    for (int i = tid; i < KCC * 16; i += 256) {
        int k = i >> 4, fx = i & 15;
        *(float4*)&qms[k * XLD + fx * 4] =
            *(const float4*)&g_qm[((size_t)b * KCC + k) * NN + n0 + fx * 4];
    }
    if (tid < KCC) zsm[tid] = g_zf[b * KCC + tid];
    __syncthreads();

    if (tid < TP) {
        float s = 0.f;
#pragma unroll
        for (int k = 0; k < KCC; k++) s = fmaf(zsm[k], qms[k * XLD + tid], s);
        invq[tid] = gamma[0] / fmaxf(s, 1e-6f);
    }
    __syncthreads();

    unsigned long long acc2[4][4];
#pragma unroll
    for (int ci = 0; ci < 4; ci++)
#pragma unroll
        for (int pj = 0; pj < 4; pj++) acc2[ci][pj] = 0ull;

#pragma unroll 4
    for (int k = 0; k < KCC; k++) {
        float4 p = *(float4*)&qms[k * XLD + tx * 4];
        unsigned long long px2[4];
        px2[0] = pack2(p.x);
        px2[1] = pack2(p.y);
        px2[2] = pack2(p.z);
        px2[3] = pack2(p.w);
        ulonglong2 A0 = *(const ulonglong2*)&kvh[k * 128 + ty * 8];
        ulonglong2 A1 = *(const ulonglong2*)&kvh[k * 128 + ty * 8 + 4];
#pragma unroll
        for (int pj = 0; pj < 4; pj++) {
            fma2(acc2[0][pj], A0.x, px2[pj]);
            fma2(acc2[1][pj], A0.y, px2[pj]);
            fma2(acc2[2][pj], A1.x, px2[pj]);
            fma2(acc2[3][pj], A1.y, px2[pj]);
        }
    }

    float iv[4];
#pragma unroll
    for (int j = 0; j < 4; j++) iv[j] = invq[tx * 4 + j];

#pragma unroll
    for (int ci = 0; ci < 4; ci++) {
        float lo[4], hi[4];
#pragma unroll
        for (int pj = 0; pj < 4; pj++) unpack2(lo[pj], hi[pj], acc2[ci][pj]);

        int c0 = half * 128 + ty * 8 + 2 * ci;
        size_t gx0 = ((size_t)b * CC + c0) * NN + n0 + tx * 4;
        float4 xv0 = *(const float4*)&x[gx0];
        float4 o0;
        o0.x = fmaf(lo[0], iv[0], xv0.x);
        o0.y = fmaf(lo[1], iv[1], xv0.y);
        o0.z = fmaf(lo[2], iv[2], xv0.z);
        o0.w = fmaf(lo[3], iv[3], xv0.w);
        *(float4*)&out[gx0] = o0;

        size_t gx1 = gx0 + NN;
        float4 xv1 = *(const float4*)&x[gx1];
        float4 o1;
        o1.x = fmaf(hi[0], iv[0], xv1.x);
        o1.y = fmaf(hi[1], iv[1], xv1.y);
        o1.z = fmaf(hi[2], iv[2], xv1.z);
        o1.w = fmaf(hi[3], iv[3], xv1.w);
        *(float4*)&out[gx1] = o1;
    }
}

// ---------------------------------------------------------------------------
extern "C" void kernel_launch(void* const* d_in, const int* in_sizes, int n_in,
                              void* d_out, int out_size)
{
    const float* x     = (const float*)d_in[0];
    const float* Wq    = (const float*)d_in[1];
    const float* bq    = (const float*)d_in[2];
    const float* Wk    = (const float*)d_in[3];
    const float* bk    = (const float*)d_in[4];
    const float* Wv    = (const float*)d_in[5];
    const float* bv    = (const float*)d_in[6];
    const float* gamma = (const float*)d_in[7];
    float* out = (float*)d_out;

    cudaFuncSetAttribute(pass1_kernel, cudaFuncAttributeMaxDynamicSharedMemorySize,
                         SMEM1_BYTES);

    zero_kernel<<<(BB * KCC * CC + 255) / 256, 256>>>();
    pass1_kernel<<<GRID1, 256, SMEM1_BYTES>>>(x, Wq, bq, Wk, bk);
    kv_kernel<<<dim3(8, BB), 256>>>(Wv, bv);
    pass2_kernel<<<dim3(NN / TP, 2, BB), 256>>>(x, gamma, out);
}